// round 17
// baseline (speedup 1.0000x reference)
#include <cuda_runtime.h>
#include <cuda_bf16.h>
#include <cuda_fp16.h>
#include <stdint.h>
#include <math.h>

// Problem constants
#define BTN   64
#define SEQ   264
#define MROWS (BTN*SEQ)      // 16896
#define GDIM  1024
#define NH    16
#define NKV   4
#define HD    64
#define QKV_N 1536
#define NZ    256

// GEMM tiling: block 128x128, BK=64, 4 warps (warptile 64x64), 3-stage
#define BK    64
#define KT    (GDIM/BK)      // 16
#define PLANE_B 16384
#define NSTG  3
#define STAGE1_B (2*PLANE_B)
#define GEMM1_SMEM (NSTG*STAGE1_B)  // 98304

// Attention smem: K + V + double-buffered Q
#define LDP   144
#define KPAD  272
#define SM_K  0
#define SM_V  (KPAD*LDP)
#define SM_Q0 (2*KPAD*LDP)          // 78336
#define SM_Q1 (SM_Q0 + 96*LDP)      // 92160
#define ATT_SMEM (SM_Q1 + 96*LDP)   // 105984

// ---------------------------------------------------------------------------
// device scratch
// ---------------------------------------------------------------------------
__device__ __align__(16) __half g_x[(size_t)MROWS * GDIM];
__device__ __align__(16) __half g_wqkv[(size_t)QKV_N * GDIM];
__device__ __align__(16) __half g_wo[(size_t)GDIM * GDIM];
__device__ __align__(16) __half g_a[(size_t)MROWS * GDIM];
__device__ __align__(16) __half g_kp[(size_t)BTN * NKV * SEQ * HD];
__device__ __align__(16) __half g_vp[(size_t)BTN * NKV * SEQ * HD];
__device__ __align__(16) __half g_qp[(size_t)BTN * NH * SEQ * HD];
__device__ float g_cos[NZ * HD];
__device__ float g_sin[NZ * HD];

// ---------------------------------------------------------------------------
// helpers
// ---------------------------------------------------------------------------
__device__ __forceinline__ uint32_t smem_u32(const void* p) {
    uint32_t a;
    asm("{ .reg .u64 t; cvta.to.shared.u64 t, %1; cvt.u32.u64 %0, t; }"
        : "=r"(a) : "l"(p));
    return a;
}
__device__ __forceinline__ void cp16(uint32_t dst, const void* src) {
    asm volatile("cp.async.cg.shared.global [%0], [%1], 16;" :: "r"(dst), "l"(src));
}
#define CP_COMMIT() asm volatile("cp.async.commit_group;" ::: "memory")
#define CP_WAIT(n)  asm volatile("cp.async.wait_group %0;" :: "n"(n) : "memory")

__device__ __forceinline__ void ldsm4(uint32_t* r, uint32_t addr) {
    asm volatile("ldmatrix.sync.aligned.m8n8.x4.shared.b16 {%0,%1,%2,%3}, [%4];"
                 : "=r"(r[0]), "=r"(r[1]), "=r"(r[2]), "=r"(r[3]) : "r"(addr));
}
__device__ __forceinline__ void ldsm4t(uint32_t* r, uint32_t addr) {
    asm volatile("ldmatrix.sync.aligned.m8n8.x4.trans.shared.b16 {%0,%1,%2,%3}, [%4];"
                 : "=r"(r[0]), "=r"(r[1]), "=r"(r[2]), "=r"(r[3]) : "r"(addr));
}
__device__ __forceinline__ void mma16816h(float* c, const uint32_t* a, const uint32_t* b) {
    asm volatile(
        "mma.sync.aligned.m16n8k16.row.col.f32.f16.f16.f32 "
        "{%0,%1,%2,%3}, {%4,%5,%6,%7}, {%8,%9}, {%0,%1,%2,%3};"
        : "+f"(c[0]), "+f"(c[1]), "+f"(c[2]), "+f"(c[3])
        : "r"(a[0]), "r"(a[1]), "r"(a[2]), "r"(a[3]), "r"(b[0]), "r"(b[1]));
}

__device__ __forceinline__ uint32_t swz(int r, int u) {
    return (uint32_t)(r * 128 + ((u ^ (r & 7)) << 4));
}

__device__ __forceinline__ float softcap_exp(float s) {
    float s2 = s * s;
    float u = s * s2 * (-1.33333333e-4f + s2 * 2.13333333e-8f);
    float corr = 1.f + u * (1.f + 0.5f * u);
    return __expf(s) * corr;
}

// ---------------------------------------------------------------------------
// init kernels
// ---------------------------------------------------------------------------
__global__ void conv_h(const float* __restrict__ src, __half* __restrict__ dst, int nunits) {
    for (int i = blockIdx.x * blockDim.x + threadIdx.x; i < nunits;
         i += gridDim.x * blockDim.x) {
        const float4 f0 = *(const float4*)(src + (size_t)i * 8);
        const float4 f1 = *(const float4*)(src + (size_t)i * 8 + 4);
        __half2 h[4];
        h[0] = __floats2half2_rn(f0.x, f0.y);
        h[1] = __floats2half2_rn(f0.z, f0.w);
        h[2] = __floats2half2_rn(f1.x, f1.y);
        h[3] = __floats2half2_rn(f1.z, f1.w);
        ((uint4*)dst)[i] = *(uint4*)h;
    }
}

// merged: pack wq/wk/wv, convert wo, rope table
__global__ void init_misc(const float* __restrict__ wq, const float* __restrict__ wk,
                          const float* __restrict__ wv, const float* __restrict__ wo) {
    int stride = gridDim.x * blockDim.x;
    int t0 = blockIdx.x * blockDim.x + threadIdx.x;
    // pack qkv weights
    for (int i = t0; i < QKV_N * (GDIM / 8); i += stride) {
        int row = i >> 7, ur = i & 127;
        const float* srow;
        if (row < NH * HD)                srow = wq + (size_t)row * GDIM;
        else if (row < NH*HD + NKV*HD)    srow = wk + (size_t)(row - NH*HD) * GDIM;
        else                              srow = wv + (size_t)(row - NH*HD - NKV*HD) * GDIM;
        const float4 f0 = *(const float4*)(srow + ur * 8);
        const float4 f1 = *(const float4*)(srow + ur * 8 + 4);
        __half2 h[4];
        h[0] = __floats2half2_rn(f0.x, f0.y);
        h[1] = __floats2half2_rn(f0.z, f0.w);
        h[2] = __floats2half2_rn(f1.x, f1.y);
        h[3] = __floats2half2_rn(f1.z, f1.w);
        ((uint4*)g_wqkv)[i] = *(uint4*)h;
    }
    // convert wo
    for (int i = t0; i < GDIM * (GDIM / 8); i += stride) {
        const float4 f0 = *(const float4*)(wo + (size_t)i * 8);
        const float4 f1 = *(const float4*)(wo + (size_t)i * 8 + 4);
        __half2 h[4];
        h[0] = __floats2half2_rn(f0.x, f0.y);
        h[1] = __floats2half2_rn(f0.z, f0.w);
        h[2] = __floats2half2_rn(f1.x, f1.y);
        h[3] = __floats2half2_rn(f1.z, f1.w);
        ((uint4*)g_wo)[i] = *(uint4*)h;
    }
    // rope table
    for (int i = t0; i < NZ * HD; i += stride) {
        int s = i >> 6, d = i & 63;
        int j = d & 15;
        float pos = ((d & 31) < 16) ? (float)(s >> 4) : (float)(s & 15);
        float invf = __expf(-(float)j * 0.57564627324851142f);
        float c, sn;
        sincosf(pos * invf, &sn, &c);
        g_cos[i] = c;
        g_sin[i] = sn;
    }
}

// ---------------------------------------------------------------------------
// fp16 GEMM core (unchanged from R16)
// ---------------------------------------------------------------------------
__device__ __forceinline__ void load_stage1(uint32_t sb, int stage,
        const __half* __restrict__ A, const __half* __restrict__ B,
        int bm, int bn, int kc, int tid) {
    uint32_t st = sb + stage * STAGE1_B;
#pragma unroll
    for (int i = 0; i < 16; i++) {
        int v = i * 128 + tid;
        int op = v >> 10;
        int w = v & 1023;
        int r = w >> 3, u = w & 7;
        const __half* base = (op == 0) ? A : B;
        int grow = ((op == 0) ? bm : bn) * 128 + r;
        const __half* g = base + (size_t)grow * GDIM + kc * BK + u * 8;
        cp16(st + op * PLANE_B + swz(r, u), g);
    }
}

template <int MODE>
__device__ __forceinline__ void gemm_body(const __half* __restrict__ A,
        const __half* __restrict__ B, float* __restrict__ outv, int ldc,
        const float* __restrict__ qnw, const float* __restrict__ knw) {
    extern __shared__ __align__(1024) char smem[];
    uint32_t sb = smem_u32(smem);
    int tid = threadIdx.x, wid = tid >> 5, lane = tid & 31;
    int bm = blockIdx.y, bn = blockIdx.x;
    int wm = wid >> 1;
    int wn = wid & 1;

    float acc[4][8][4];
#pragma unroll
    for (int a = 0; a < 4; a++)
#pragma unroll
        for (int b = 0; b < 8; b++)
#pragma unroll
            for (int c = 0; c < 4; c++) acc[a][b][c] = 0.f;

    load_stage1(sb, 0, A, B, bm, bn, 0, tid); CP_COMMIT();
    load_stage1(sb, 1, A, B, bm, bn, 1, tid); CP_COMMIT();

    for (int kc = 0; kc < KT; kc++) {
        CP_WAIT(1);
        __syncthreads();
        if (kc + 2 < KT)
            load_stage1(sb, (kc + 2) % NSTG, A, B, bm, bn, kc + 2, tid);
        CP_COMMIT();

        uint32_t st = sb + (kc % NSTG) * STAGE1_B;
#pragma unroll
        for (int ks = 0; ks < 4; ks++) {
            uint32_t af[4][4], bf[8][2];
#pragma unroll
            for (int mt = 0; mt < 4; mt++) {
                int r = wm * 64 + mt * 16 + (lane & 15);
                int u = 2 * ks + (lane >> 4);
                ldsm4(af[mt], st + swz(r, u));
            }
#pragma unroll
            for (int np = 0; np < 4; np++) {
                int r = wn * 64 + np * 16 + (lane & 7) + ((lane >> 4) & 1) * 8;
                int u = 2 * ks + ((lane >> 3) & 1);
                uint32_t t[4];
                ldsm4(t, st + PLANE_B + swz(r, u));
                bf[np*2][0] = t[0]; bf[np*2][1] = t[1];
                bf[np*2+1][0] = t[2]; bf[np*2+1][1] = t[3];
            }
#pragma unroll
            for (int mt = 0; mt < 4; mt++)
#pragma unroll
                for (int nt = 0; nt < 8; nt++) mma16816h(acc[mt][nt], af[mt], bf[nt]);
        }
    }

    if (MODE == 0) {
#pragma unroll
        for (int mt = 0; mt < 4; mt++)
#pragma unroll
            for (int nt = 0; nt < 8; nt++) {
                float* c = acc[mt][nt];
                int row = bm * 128 + wm * 64 + mt * 16 + (lane >> 2);
                int col = bn * 128 + wn * 64 + nt * 8 + 2 * (lane & 3);
                *(float2*)(outv + (size_t)row * ldc + col) = make_float2(c[0], c[1]);
                *(float2*)(outv + (size_t)(row + 8) * ldc + col) = make_float2(c[2], c[3]);
            }
    } else {
        int H = bn * 2 + wn;
        bool isv = (H >= NH + NKV);
        bool isq = (H < NH);
        const float* nw = isq ? qnw : knw;
        int d0 = 2 * (lane & 3);
#pragma unroll
        for (int mt = 0; mt < 4; mt++) {
#pragma unroll
            for (int half = 0; half < 2; half++) {
                int row = bm * 128 + wm * 64 + mt * 16 + (lane >> 2) + half * 8;
                int bt = row / SEQ, s = row - bt * SEQ;
                float v[16];
#pragma unroll
                for (int nt = 0; nt < 8; nt++) {
                    v[nt*2]   = acc[mt][nt][half*2];
                    v[nt*2+1] = acc[mt][nt][half*2+1];
                }
                __half* dst;
                size_t o;
                if (isv) {
                    o = ((size_t)(bt * NKV + (H - NH - NKV)) * SEQ + s) * HD;
                    dst = g_vp;
                } else {
                    float ss = 0.f;
#pragma unroll
                    for (int i = 0; i < 16; i++) ss += v[i] * v[i];
                    ss += __shfl_xor_sync(0xffffffffu, ss, 1);
                    ss += __shfl_xor_sync(0xffffffffu, ss, 2);
                    float scl = rsqrtf(ss * (1.0f / HD) + 1e-6f);
#pragma unroll
                    for (int i = 0; i < 16; i++) {
                        int d = (i >> 1) * 8 + d0 + (i & 1);
                        v[i] *= scl * nw[d];
                    }
                    if (s < NZ) {
                        float t[16];
#pragma unroll
                        for (int i = 0; i < 16; i++) {
                            int d = (i >> 1) * 8 + d0 + (i & 1);
                            float cs = g_cos[s * HD + d];
                            float sn = g_sin[s * HD + d];
                            float rot = (d < 32) ? -v[(i + 8) & 15] : v[(i + 8) & 15];
                            t[i] = v[i] * cs + rot * sn;
                        }
#pragma unroll
                        for (int i = 0; i < 16; i++) v[i] = t[i];
                    }
                    if (isq) {
                        o = ((size_t)(bt * NH + H) * SEQ + s) * HD;
                        dst = g_qp;
                    } else {
                        o = ((size_t)(bt * NKV + (H - NH)) * SEQ + s) * HD;
                        dst = g_kp;
                    }
                }
#pragma unroll
                for (int nt = 0; nt < 8; nt++) {
                    *(__half2*)(dst + o + nt * 8 + d0) =
                        __floats2half2_rn(v[nt*2], v[nt*2+1]);
                }
            }
        }
    }
}

__global__ __launch_bounds__(128, 2)
void gemm_f32(const __half* __restrict__ A, const __half* __restrict__ B,
              float* __restrict__ out, int ldc) {
    gemm_body<0>(A, B, out, ldc, nullptr, nullptr);
}
__global__ __launch_bounds__(128, 2)
void gemm_qkv(const __half* __restrict__ A, const __half* __restrict__ B,
              const float* __restrict__ qnw, const float* __restrict__ knw) {
    gemm_body<1>(A, B, nullptr, 0, qnw, knw);
}

// ---------------------------------------------------------------------------
// Attention: grid (3 m-tiles, NKV, BTN); KV loaded once, 4 q-heads processed
// sequentially with double-buffered Q prefetch. 2 CTA/SM.
// ---------------------------------------------------------------------------
__global__ __launch_bounds__(192, 2) void attn_mma() {
    extern __shared__ __align__(1024) char smem[];
    const int tid = threadIdx.x;
    const int mt = blockIdx.x, kvh = blockIdx.y, bt = blockIdx.z;
    const int m0 = (mt == 0) ? 0 : (mt == 1 ? 96 : 168);
    const uint32_t sb = smem_u32(smem);

    size_t kvo = (size_t)(bt * NKV + kvh) * SEQ * HD;
    const __half* k_g = g_kp + kvo;
    const __half* v_g = g_vp + kvo;

    // ---- load K/V once + Q of head 0 ----
    for (int idx = tid; idx < SEQ * 8; idx += 192) {
        int r = idx >> 3, u = idx & 7;
        uint32_t doff = (uint32_t)(r * LDP + u * 16);
        int soff = r * HD + u * 8;
        cp16(sb + SM_K + doff, k_g + soff);
        cp16(sb + SM_V + doff, v_g + soff);
    }
    {
        size_t qo = ((size_t)(bt * NH + kvh * 4) * SEQ + m0) * HD;
        const __half* q_g = g_qp + qo;
        for (int idx = tid; idx < 96 * 8; idx += 192) {
            int r = idx >> 3, u = idx & 7;
            cp16(sb + SM_Q0 + (uint32_t)(r * LDP + u * 16), q_g + r * HD + u * 8);
        }
    }
    for (int idx = tid; idx < 8 * 36; idx += 192) {
        int off = (SEQ + idx / 36) * LDP + (idx % 36) * 4;
        *(uint32_t*)(smem + SM_K + off) = 0;
        *(uint32_t*)(smem + SM_V + off) = 0;
    }
    CP_COMMIT();

    const int w = tid >> 5, lane = tid & 31;
    const int krow = (lane & 7) + ((lane >> 4) & 1) * 8;
    const int ku = (lane >> 3) & 1;
    const int vrow = (lane & 7) + ((lane >> 3) & 1) * 8;
    const int vu = (lane >> 4) & 1;

    for (int hh = 0; hh < 4; hh++) {
        const int h = kvh * 4 + hh;
        const uint32_t qbuf = (hh & 1) ? SM_Q1 : SM_Q0;

        CP_WAIT(0);
        __syncthreads();

        // load q fragments for this head
        uint32_t qh[4][4];
        {
            int r = w * 16 + (lane & 15);
            int uo = lane >> 4;
#pragma unroll
            for (int kc = 0; kc < 4; kc++)
                ldsm4(qh[kc], sb + qbuf + (uint32_t)(r * LDP + (2 * kc + uo) * 16));
        }
        __syncthreads();   // all warps consumed qbuf before prefetch overwrites sibling

        // prefetch next head's Q into the other buffer
        if (hh < 3) {
            size_t qo = ((size_t)(bt * NH + h + 1) * SEQ + m0) * HD;
            const __half* q_g = g_qp + qo;
            uint32_t nbuf = (hh & 1) ? SM_Q0 : SM_Q1;
            for (int idx = tid; idx < 96 * 8; idx += 192) {
                int r = idx >> 3, u = idx & 7;
                cp16(sb + nbuf + (uint32_t)(r * LDP + u * 16), q_g + r * HD + u * 8);
            }
        }
        CP_COMMIT();

        float oacc[8][4];
#pragma unroll
        for (int i = 0; i < 8; i++)
#pragma unroll
            for (int j = 0; j < 4; j++) oacc[i][j] = 0.f;
        float lsum0 = 0.f, lsum1 = 0.f;

        for (int np = 0; np < 17; np++) {
            float sA0[4] = {0,0,0,0}, sA1[4] = {0,0,0,0};
#pragma unroll
            for (int kc = 0; kc < 4; kc++) {
                uint32_t off = (uint32_t)((np * 16 + krow) * LDP + (2 * kc + ku) * 16);
                uint32_t bh[4];
                ldsm4(bh, sb + SM_K + off);
                mma16816h(sA0, qh[kc], bh);
                mma16816h(sA1, qh[kc], bh + 2);
            }
            float pf[2][4];
#pragma unroll
            for (int e = 0; e < 4; e++) {
                pf[0][e] = softcap_exp(sA0[e] * 0.125f);
                pf[1][e] = softcap_exp(sA1[e] * 0.125f);
            }
            if (np == 16) { pf[1][0] = pf[1][1] = pf[1][2] = pf[1][3] = 0.f; }
            lsum0 += pf[0][0] + pf[0][1] + pf[1][0] + pf[1][1];
            lsum1 += pf[0][2] + pf[0][3] + pf[1][2] + pf[1][3];

            uint32_t ph[4];
            __half2 p0 = __floats2half2_rn(pf[0][0], pf[0][1]);
            __half2 p1 = __floats2half2_rn(pf[0][2], pf[0][3]);
            __half2 p2 = __floats2half2_rn(pf[1][0], pf[1][1]);
            __half2 p3 = __floats2half2_rn(pf[1][2], pf[1][3]);
            ph[0] = *(uint32_t*)&p0; ph[1] = *(uint32_t*)&p1;
            ph[2] = *(uint32_t*)&p2; ph[3] = *(uint32_t*)&p3;

            uint32_t vh[4][4];
#pragma unroll
            for (int db = 0; db < 4; db++) {
                uint32_t off = (uint32_t)((np * 16 + vrow) * LDP + (2 * db + vu) * 16);
                ldsm4t(vh[db], sb + SM_V + off);
            }
#pragma unroll
            for (int db = 0; db < 4; db++) {
                mma16816h(oacc[2*db],   ph, vh[db]);
                mma16816h(oacc[2*db+1], ph, vh[db] + 2);
            }
        }

        lsum0 += __shfl_xor_sync(0xffffffffu, lsum0, 1);
        lsum0 += __shfl_xor_sync(0xffffffffu, lsum0, 2);
        lsum1 += __shfl_xor_sync(0xffffffffu, lsum1, 1);
        lsum1 += __shfl_xor_sync(0xffffffffu, lsum1, 2);
        float inv0 = __fdividef(1.f, lsum0);
        float inv1 = __fdividef(1.f, lsum1);

        size_t row0 = (size_t)bt * SEQ + m0 + w * 16 + (lane >> 2);
        int colb = h * HD + 2 * (lane & 3);
#pragma unroll
        for (int nb = 0; nb < 8; nb++) {
            int col = colb + nb * 8;
            *(__half2*)(g_a + row0 * GDIM + col) =
                __floats2half2_rn(oacc[nb][0] * inv0, oacc[nb][1] * inv0);
            *(__half2*)(g_a + (row0 + 8) * GDIM + col) =
                __floats2half2_rn(oacc[nb][2] * inv1, oacc[nb][3] * inv1);
        }
    }
}

// ---------------------------------------------------------------------------
extern "C" void kernel_launch(void* const* d_in, const int* in_sizes, int n_in,
                              void* d_out, int out_size) {
    const float* x   = (const float*)d_in[0];
    const float* wq  = (const float*)d_in[1];
    const float* wk  = (const float*)d_in[2];
    const float* wv  = (const float*)d_in[3];
    const float* wo  = (const float*)d_in[4];
    const float* qnw = (const float*)d_in[5];
    const float* knw = (const float*)d_in[6];
    float* out = (float*)d_out;

    __half *xh, *wqkvh, *woh, *ah;
    cudaGetSymbolAddress((void**)&xh, g_x);
    cudaGetSymbolAddress((void**)&wqkvh, g_wqkv);
    cudaGetSymbolAddress((void**)&woh, g_wo);
    cudaGetSymbolAddress((void**)&ah, g_a);

    cudaFuncSetAttribute((const void*)gemm_f32,
                         cudaFuncAttributeMaxDynamicSharedMemorySize, GEMM1_SMEM);
    cudaFuncSetAttribute((const void*)gemm_qkv,
                         cudaFuncAttributeMaxDynamicSharedMemorySize, GEMM1_SMEM);
    cudaFuncSetAttribute((const void*)attn_mma,
                         cudaFuncAttributeMaxDynamicSharedMemorySize, ATT_SMEM);

    // 1) operand conversion (merged small inits + big x conversion)
    init_misc<<<640, 256>>>(wq, wk, wv, wo);
    conv_h<<<4224, 256>>>(x, xh, MROWS * GDIM / 8);

    // 2) QKV projection with fused QKNorm + RoPE + plane scatter
    gemm_qkv<<<dim3(QKV_N / 128, MROWS / 128), 128, GEMM1_SMEM>>>(
        xh, wqkvh, qnw, knw);

    // 3) tensor-core attention (KV loaded once per GQA group)
    attn_mma<<<dim3(3, NKV, BTN), 192, ATT_SMEM>>>();

    // 4) output projection
    gemm_f32<<<dim3(GDIM / 128, MROWS / 128), 128, GEMM1_SMEM>>>(
        ah, woh, out, GDIM);
}